// round 4
// baseline (speedup 1.0000x reference)
#include <cuda_runtime.h>

#define DD 64
#define HH 128
#define WW 128
#define NVOX (DD*HH*WW)

// padded layout: z pad 2 (68), y pad 2 (132), x pad 4/+ (136, 16B-aligned rows)
#define PH 132
#define PW 136
#define PPLANE (PH*PW)
#define PSZ (68*PPLANE)

// ---- static device state (zero-initialized -> padding borders stay 0 forever) ----
__device__ float g_qA[PSZ];
__device__ float g_qB[PSZ];
__device__ float g_img[PSZ];
__device__ float g_du[NVOX];
__device__ float g_coef[4];   // dA0, dA1-dA0, dB0, dB1-dB0

// ---- blur taps (sigma=1, radius 2, normalized) ----
constexpr double c_E05 = 0.60653065971263342426;
constexpr double c_E2  = 0.13533528323661269189;
constexpr double c_KS  = 1.0 + 2.0*c_E05 + 2.0*c_E2;
#define K0F ((float)(1.0   / c_KS))
#define K1F ((float)(c_E05 / c_KS))
#define K2F ((float)(c_E2  / c_KS))

// bilateral: w = sc[d2]*exp(-2*df^2) = 2^(CEXP*df^2 + LSC[d2])
#define CEXP  (-2.8853900817779268f)   // -2*log2(e)
#define LSC1  (-0.3205988979944306f)
#define LSC2  (-0.6411977959888612f)
#define LSC3  (-0.9617966939832918f)

#define LOG_SQRT_2PI 0.91893853320467274178f

__device__ __forceinline__ float ex2f(float x) {
    float r; asm("ex2.approx.ftz.f32 %0, %1;" : "=f"(r) : "f"(x)); return r;
}
__device__ __forceinline__ float sigmoidf_fast(float x) {
    return __fdividef(1.0f, 1.0f + ex2f(-1.4426950408889634f * x));
}
__device__ __forceinline__ int pidx(int z, int y, int x) {
    return ((z + 2)*PH + (y + 2))*PW + (x + 4);
}
// missing-tap mass for blur-of-ones along one axis
__device__ __forceinline__ float axis_sum(int i, int N) {
    float m = 1.f;
    if (i == 0) m -= (K1F + K2F); else if (i == 1) m -= K2F;
    int j = N - 1 - i;
    if (j == 0) m -= (K1F + K2F); else if (j == 1) m -= K2F;
    return m;
}

__global__ void init_kernel(const float* __restrict__ img,
                            const float* __restrict__ h,
                            const float* __restrict__ f1,
                            const float* __restrict__ w0,
                            const float* __restrict__ sw,
                            const float* __restrict__ bw,
                            const float* __restrict__ cm) {
    int i4 = blockIdx.x * blockDim.x + threadIdx.x;
    if (i4 >= NVOX / 4) return;
    if (i4 == 0) {
        float cm0 = cm[2] - cm[0];
        float cm1 = cm[3] - cm[1];
        float dA0 = cm0 * sw[0] + cm1 * sw[2];
        float dA1 = cm0 * sw[1] + cm1 * sw[3];
        float dB0 = cm0 * bw[0] + cm1 * bw[2];
        float dB1 = cm0 * bw[1] + cm1 * bw[3];
        g_coef[0] = dA0; g_coef[1] = dA1 - dA0;
        g_coef[2] = dB0; g_coef[3] = dB1 - dB0;
    }
    // decode voxel coords (WW/4=32, HH=128 pow2)
    int x4 = (i4 & 31) << 2;
    int r  = i4 >> 5;
    int y  = r & 127;
    int z  = r >> 7;

    float4 I  = ((const float4*)img)[i4];
    float4 h0 = ((const float4*)h)[i4];
    float4 h1 = ((const float4*)h)[i4 + NVOX/4];
    float4 F  = ((const float4*)f1)[i4];
    float wv = w0[0];
    float4 d, du, q;
    d.x = h1.x - h0.x; d.y = h1.y - h0.y; d.z = h1.z - h0.z; d.w = h1.w - h0.w;
    du.x = d.x * (F.x - wv + 0.5f*I.x*I.x + LOG_SQRT_2PI);
    du.y = d.y * (F.y - wv + 0.5f*I.y*I.y + LOG_SQRT_2PI);
    du.z = d.z * (F.z - wv + 0.5f*I.z*I.z + LOG_SQRT_2PI);
    du.w = d.w * (F.w - wv + 0.5f*I.w*I.w + LOG_SQRT_2PI);
    q.x = sigmoidf_fast(d.x); q.y = sigmoidf_fast(d.y);
    q.z = sigmoidf_fast(d.z); q.w = sigmoidf_fast(d.w);
    ((float4*)g_du)[i4] = du;
    int p = pidx(z, y, x4);
    *(float4*)&g_qA[p]  = q;
    *(float4*)&g_img[p] = I;
}

// ---- 27-tap bilateral -> pairwise contribution (scalar, offsets fold to immediates) ----
template<int EDGE>
__device__ __forceinline__ float bilat_pb(const float* __restrict__ qc,
                                          const float* __restrict__ ic,
                                          const float vz[3], const float vy[3], const float vx[3],
                                          float dB0, float dB1m)
{
    const float Ic = ic[0];
    float acc = 0.f, den = 0.f, vs = 0.f;
    #pragma unroll
    for (int dz = -1; dz <= 1; dz++) {
        #pragma unroll
        for (int dy = -1; dy <= 1; dy++) {
            #pragma unroll
            for (int dx = -1; dx <= 1; dx++) {
                const int d2  = dz*dz + dy*dy + dx*dx;
                const int off = dz*144 + dy*12 + dx;
                if (d2 == 0) {
                    den += 1.f;
                    acc += qc[0];
                    if (EDGE) vs += 1.f;
                } else {
                    const float lsc = (d2 == 1) ? LSC1 : (d2 == 2) ? LSC2 : LSC3;
                    float df = Ic - ic[off];
                    float w  = ex2f(fmaf(df*df, CEXP, lsc));
                    den += w;
                    acc = fmaf(w, qc[off], acc);
                    if (EDGE) vs = fmaf(w, vz[dz+1]*vy[dy+1]*vx[dx+1], vs);
                }
            }
        }
    }
    if (EDGE) return __fdividef(dB0*vs + dB1m*acc, den);
    return dB0 + dB1m * __fdividef(acc, den);
}

template<int LAST>
__global__ void __launch_bounds__(512, 4)
iter_kernel(int flip, float* __restrict__ out,
            const float* __restrict__ f1, int copyf1)
{
    __shared__ float sq[12][12][12];
    __shared__ float si[12][12][12];
    __shared__ float t1[12][12][8];
    __shared__ float t2[12][8][8];

    const float* __restrict__ qprev = flip ? g_qB : g_qA;
    float*       __restrict__ qnext = flip ? g_qA : g_qB;

    const int tx = threadIdx.x, ty = threadIdx.y, tz = threadIdx.z;
    const int tid = tx + (ty << 3) + (tz << 6);
    const int x0 = blockIdx.x << 3, y0 = blockIdx.y << 3, z0 = blockIdx.z << 3;

    // ---- branch-free halo load (padded global; borders are hard zeros) ----
    // smem elem (lz,ly,lx) <-> padded addr pbase + lz*PPLANE + ly*PW + lx
    const int pbase = (z0*PH + y0)*PW + x0 + 2;
    float* __restrict__ sqf = &sq[0][0][0];
    float* __restrict__ sif = &si[0][0][0];
    #pragma unroll
    for (int e = tid; e < 1728; e += 512) {
        int lz = e / 144;
        int r  = e - lz*144;
        int ly = r / 12;
        int lx = r - ly*12;
        int a  = pbase + lz*PPLANE + ly*PW + lx;
        sqf[e] = qprev[a];
        sif[e] = g_img[a];
    }
    __syncthreads();

    // ---- x-blur (1152 elems) ----
    #pragma unroll
    for (int e = tid; e < 1152; e += 512) {
        int lz = e / 96;
        int r  = e - lz*96;
        int ly = r >> 3;
        int xx = r & 7;
        const float* row = &sq[lz][ly][xx];
        t1[lz][ly][xx] = K2F*(row[0] + row[4]) + K1F*(row[1] + row[3]) + K0F*row[2];
    }
    __syncthreads();

    // ---- y-blur (768 elems) ----
    #pragma unroll
    for (int e = tid; e < 768; e += 512) {
        int lz = e >> 6;
        int r  = e & 63;
        int yy = r >> 3;
        int xx = r & 7;
        t2[lz][yy][xx] = K2F*(t1[lz][yy  ][xx] + t1[lz][yy+4][xx])
                       + K1F*(t1[lz][yy+1][xx] + t1[lz][yy+3][xx])
                       + K0F* t1[lz][yy+2][xx];
    }
    __syncthreads();

    // ---- per-voxel tail: bilateral + z-blur + combine (no more barriers) ----
    const int gx = x0 + tx, gy = y0 + ty, gz = z0 + tz;
    const int gi = (gz*HH + gy)*WW + gx;
    const float duv  = g_du[gi];
    const float dA0  = g_coef[0];
    const float dA1m = g_coef[1];
    const float dB0  = g_coef[2];
    const float dB1m = g_coef[3];

    const float* qc = &sq[tz+2][ty+2][tx+2];
    const float* ic = &si[tz+2][ty+2][tx+2];

    float pb;
    bool edge = (gx == 0) | (gx == WW-1) | (gy == 0) | (gy == HH-1) |
                (gz == 0) | (gz == DD-1);
    if (!edge) {
        pb = bilat_pb<0>(qc, ic, nullptr, nullptr, nullptr, dB0, dB1m);
    } else {
        float vz[3] = { gz > 0 ? 1.f : 0.f, 1.f, gz < DD-1 ? 1.f : 0.f };
        float vy[3] = { gy > 0 ? 1.f : 0.f, 1.f, gy < HH-1 ? 1.f : 0.f };
        float vx[3] = { gx > 0 ? 1.f : 0.f, 1.f, gx < WW-1 ? 1.f : 0.f };
        pb = bilat_pb<1>(qc, ic, vz, vy, vx, dB0, dB1m);
    }

    float sp = K2F*(t2[tz][ty][tx]   + t2[tz+4][ty][tx])
             + K1F*(t2[tz+1][ty][tx] + t2[tz+3][ty][tx])
             + K0F* t2[tz+2][ty][tx];

    float S = axis_sum(gz, DD) * axis_sum(gy, HH) * axis_sum(gx, WW);
    float res = sigmoidf_fast(duv - (dA0*S + dA1m*sp + pb));

    if (LAST) {
        out[gi]        = 1.f - res;
        out[NVOX + gi] = res;
        if (copyf1) out[2*NVOX + gi] = f1[gi];
    } else {
        qnext[pidx(gz, gy, gx)] = res;
    }
}

extern "C" void kernel_launch(void* const* d_in, const int* in_sizes, int n_in,
                              void* d_out, int out_size) {
    const float* img = (const float*)d_in[0];
    const float* h   = (const float*)d_in[1];
    const float* f1  = (const float*)d_in[2];
    const float* w0  = (const float*)d_in[3];
    const float* sw  = (const float*)d_in[4];
    const float* bw  = (const float*)d_in[5];
    const float* cm  = (const float*)d_in[6];
    float* out = (float*)d_out;

    init_kernel<<<NVOX/4/256, 256>>>(img, h, f1, w0, sw, bw, cm);

    dim3 blk(8, 8, 8);
    dim3 grd(WW/8, HH/8, DD/8);
    int copyf1 = (out_size >= 3 * NVOX) ? 1 : 0;
    // it 0..3 regular, it 4 fused with output
    iter_kernel<0><<<grd, blk>>>(0, out, f1, copyf1);
    iter_kernel<0><<<grd, blk>>>(1, out, f1, copyf1);
    iter_kernel<0><<<grd, blk>>>(0, out, f1, copyf1);
    iter_kernel<0><<<grd, blk>>>(1, out, f1, copyf1);
    iter_kernel<1><<<grd, blk>>>(0, out, f1, copyf1);
}

// round 5
// speedup vs baseline: 2.0175x; 2.0175x over previous
#include <cuda_runtime.h>

#define DD 64
#define HH 128
#define WW 128
#define NVOX (DD*HH*WW)

// padded layout (zero borders, zero-initialized statics)
#define PH 132
#define PW 136
#define PPLANE (PH*PW)
#define PSZ (68*PPLANE)

// ---- static device state ----
__device__ float2 g_pA[PSZ];    // (img, q) padded
__device__ float2 g_pB[PSZ];
__device__ float  g_duS[NVOX];  // du - dA0*S  (unary diff minus static spatial-ones term)
__device__ float  g_coef[4];    // dA0, dA1-dA0, dB0, dB1-dB0

// ---- blur taps (sigma=1, radius 2, normalized) ----
constexpr double c_E05 = 0.60653065971263342426;
constexpr double c_E2  = 0.13533528323661269189;
constexpr double c_KS  = 1.0 + 2.0*c_E05 + 2.0*c_E2;
#define K0F ((float)(1.0   / c_KS))
#define K1F ((float)(c_E05 / c_KS))
#define K2F ((float)(c_E2  / c_KS))

// bilateral: w = sc[d2]*exp(-2*df^2) = 2^(CEXP*df^2 + LSC[d2])
#define CEXP  (-2.8853900817779268f)   // -2*log2(e)
#define LSC1  (-0.3205988979944306f)
#define LSC2  (-0.6411977959888612f)
#define LSC3  (-0.9617966939832918f)

#define LOG_SQRT_2PI 0.91893853320467274178f

__device__ __forceinline__ float ex2f(float x) {
    float r; asm("ex2.approx.ftz.f32 %0, %1;" : "=f"(r) : "f"(x)); return r;
}
__device__ __forceinline__ float sigmoidf_fast(float x) {
    return __fdividef(1.0f, 1.0f + ex2f(-1.4426950408889634f * x));
}
__device__ __forceinline__ float axis_sum(int i, int N) {
    float m = 1.f;
    if (i == 0) m -= (K1F + K2F); else if (i == 1) m -= K2F;
    int j = N - 1 - i;
    if (j == 0) m -= (K1F + K2F); else if (j == 1) m -= K2F;
    return m;
}

__global__ void init_kernel(const float* __restrict__ img,
                            const float* __restrict__ h,
                            const float* __restrict__ f1,
                            const float* __restrict__ w0,
                            const float* __restrict__ sw,
                            const float* __restrict__ bw,
                            const float* __restrict__ cm) {
    int i = blockIdx.x * blockDim.x + threadIdx.x;
    if (i >= NVOX) return;
    // label-mixing scalars computed locally (cheap broadcast loads)
    float cm0 = cm[2] - cm[0];
    float cm1 = cm[3] - cm[1];
    float dA0 = cm0 * sw[0] + cm1 * sw[2];
    if (i == 0) {
        float dA1 = cm0 * sw[1] + cm1 * sw[3];
        float dB0 = cm0 * bw[0] + cm1 * bw[2];
        float dB1 = cm0 * bw[1] + cm1 * bw[3];
        g_coef[0] = dA0; g_coef[1] = dA1 - dA0;
        g_coef[2] = dB0; g_coef[3] = dB1 - dB0;
    }
    int x = i & 127;
    int y = (i >> 7) & 127;
    int z = i >> 14;

    float I  = img[i];
    float d  = h[i + NVOX] - h[i];
    float du = d * (f1[i] - w0[0] + 0.5f*I*I + LOG_SQRT_2PI);
    float S  = axis_sum(z, DD) * axis_sum(y, HH) * axis_sum(x, WW);
    g_duS[i] = du - dA0 * S;

    float q = sigmoidf_fast(d);
    int p = ((z + 2)*PH + (y + 2))*PW + (x + 4);
    g_pA[p] = make_float2(I, q);
}

template<int LAST>
__global__ void __launch_bounds__(512, 3)
iter_kernel(int flip, float* __restrict__ out,
            const float* __restrict__ f1, int copyf1)
{
    __shared__ float  sq[8][8][36];      // q (blur input), halo2, origin (z0-2,y0-2,x0-2)
    __shared__ float2 sis[6][6][34];     // (img, s=dB0*m+dB1m*q), halo1, origin (z0-1,y0-1,x0-1)
    __shared__ float  t1[8][8][32];      // x-blurred
    __shared__ float  t2[8][4][32];      // xy-blurred

    const float2* __restrict__ qprev = flip ? g_pB : g_pA;
    float2*       __restrict__ qnext = flip ? g_pA : g_pB;

    const int lane = threadIdx.x;                 // 0..31
    const int ty   = threadIdx.y;                 // 0..3
    const int tz   = threadIdx.z;                 // 0..3
    const int wid  = ty + 4*tz;                   // 0..15
    const int x0 = blockIdx.x << 5;
    const int y0 = blockIdx.y << 2;
    const int z0 = blockIdx.z << 2;

    const float dA1m = g_coef[1];
    const float dB0  = g_coef[2];
    const float dB1m = g_coef[3];

    // padded index of (z0-2, y0-2, x0-2)
    const int pbase = (z0*PH + y0)*PW + x0 + 2;

    // ---- halo load: 64 rows (8z x 8y) of 36, 4 rows per warp ----
    #pragma unroll
    for (int k = 0; k < 4; k++) {
        int r  = wid + (k << 4);
        int lz = r >> 3;
        int ly = r & 7;
        int a  = pbase + lz*PPLANE + ly*PW + lane;
        float2 v = qprev[a];
        sq[lz][ly][lane] = v.y;
        float2 vt = make_float2(0.f, 0.f);
        if (lane < 4) {
            vt = qprev[a + 32];
            sq[lz][ly][lane + 32] = vt.y;
        }
        // sis subset: lz in [1,6], ly in [1,6]  (warp-uniform branch)
        if ((unsigned)(lz - 1) < 6u && (unsigned)(ly - 1) < 6u) {
            bool zyok = ((unsigned)(z0 - 2 + lz) < (unsigned)DD) &
                        ((unsigned)(y0 - 2 + ly) < (unsigned)HH);
            // main lanes: global x = x0-2+lane, sis x index lane-1 (lane>=1)
            bool v1 = zyok & ((unsigned)(x0 - 2 + lane) < (unsigned)WW);
            float s1 = fmaf(dB1m, v.y, v1 ? dB0 : 0.f);
            if (lane >= 1) sis[lz-1][ly-1][lane-1] = make_float2(v.x, s1);
            // tail lanes: global x = x0+30+lane, sis x index lane+31 (lane<3)
            if (lane < 3) {
                bool v2 = zyok & ((unsigned)(x0 + 30 + lane) < (unsigned)WW);
                float s2 = fmaf(dB1m, vt.y, v2 ? dB0 : 0.f);
                sis[lz-1][ly-1][lane+31] = make_float2(vt.x, s2);
            }
        }
    }
    __syncthreads();

    // ---- x-blur: 64 rows, 4 per warp ----
    #pragma unroll
    for (int k = 0; k < 4; k++) {
        int r  = wid + (k << 4);
        int lz = r >> 3;
        int ly = r & 7;
        const float* row = &sq[lz][ly][lane];
        t1[lz][ly][lane] = K2F*(row[0] + row[4]) + K1F*(row[1] + row[3]) + K0F*row[2];
    }
    __syncthreads();

    // ---- y-blur: 32 rows, 2 per warp ----
    #pragma unroll
    for (int k = 0; k < 2; k++) {
        int r  = wid + (k << 4);
        int lz = r >> 2;
        int yy = r & 3;
        t2[lz][yy][lane] = K2F*(t1[lz][yy  ][lane] + t1[lz][yy+4][lane])
                         + K1F*(t1[lz][yy+1][lane] + t1[lz][yy+3][lane])
                         + K0F* t1[lz][yy+2][lane];
    }
    __syncthreads();

    // ---- z-blur (per-thread) ----
    float sp = K2F*(t2[tz][ty][lane]   + t2[tz+4][ty][lane])
             + K1F*(t2[tz+1][ty][lane] + t2[tz+3][ty][lane])
             + K0F* t2[tz+2][ty][lane];

    // ---- bilateral: 27 taps, single uniform path ----
    const float2* C = &sis[tz+1][ty+1][lane+1];
    float2 ctr = C[0];
    const float Ic = ctr.x;
    float den = 1.f;          // center weight = 1 exactly
    float acc = ctr.y;
    #pragma unroll
    for (int dz = -1; dz <= 1; dz++) {
        #pragma unroll
        for (int dy = -1; dy <= 1; dy++) {
            #pragma unroll
            for (int dx = -1; dx <= 1; dx++) {
                const int d2 = dz*dz + dy*dy + dx*dx;
                if (d2 == 0) continue;
                const int off = (dz*6 + dy)*34 + dx;
                const float lsc = (d2 == 1) ? LSC1 : (d2 == 2) ? LSC2 : LSC3;
                float2 nb = C[off];
                float df = Ic - nb.x;
                float w  = ex2f(fmaf(df*df, CEXP, lsc));
                den += w;
                acc = fmaf(w, nb.y, acc);
            }
        }
    }

    // ---- combine + write ----
    const int gx = x0 + lane, gy = y0 + ty, gz = z0 + tz;
    const int gi = (gz*HH + gy)*WW + gx;
    float d = g_duS[gi] - dA1m*sp - __fdividef(acc, den);
    float res = sigmoidf_fast(d);

    if (LAST) {
        out[gi]        = 1.f - res;
        out[NVOX + gi] = res;
        if (copyf1) out[2*NVOX + gi] = f1[gi];
    } else {
        int pc = pbase + (tz+2)*PPLANE + (ty+2)*PW + (lane + 2);
        qnext[pc] = make_float2(Ic, res);
    }
}

extern "C" void kernel_launch(void* const* d_in, const int* in_sizes, int n_in,
                              void* d_out, int out_size) {
    const float* img = (const float*)d_in[0];
    const float* h   = (const float*)d_in[1];
    const float* f1  = (const float*)d_in[2];
    const float* w0  = (const float*)d_in[3];
    const float* sw  = (const float*)d_in[4];
    const float* bw  = (const float*)d_in[5];
    const float* cm  = (const float*)d_in[6];
    float* out = (float*)d_out;

    init_kernel<<<NVOX/256, 256>>>(img, h, f1, w0, sw, bw, cm);

    dim3 blk(32, 4, 4);
    dim3 grd(WW/32, HH/4, DD/4);
    int copyf1 = (out_size >= 3 * NVOX) ? 1 : 0;
    iter_kernel<0><<<grd, blk>>>(0, out, f1, copyf1);   // A -> B
    iter_kernel<0><<<grd, blk>>>(1, out, f1, copyf1);   // B -> A
    iter_kernel<0><<<grd, blk>>>(0, out, f1, copyf1);   // A -> B
    iter_kernel<0><<<grd, blk>>>(1, out, f1, copyf1);   // B -> A
    iter_kernel<1><<<grd, blk>>>(0, out, f1, copyf1);   // A -> out
}

// round 6
// speedup vs baseline: 2.1639x; 1.0726x over previous
#include <cuda_runtime.h>

#define DD 64
#define HH 128
#define WW 128
#define NVOX (DD*HH*WW)

// padded layout (zero borders, zero-initialized statics)
#define PH 132
#define PW 136
#define PPLANE (PH*PW)
#define PSZ (68*PPLANE)

// ---- static device state ----
// (I, s) where s = dB1m*q + dB0*m; padding stays (0,0) forever = mask 0.
__device__ float2 g_pA[PSZ];
__device__ float2 g_pB[PSZ];
__device__ float  g_duS2[NVOX];  // du - (dA0 - rB*dB0)*S
__device__ float  g_coef[4];     // rB, dB0, dB1m, -

// ---- blur taps (sigma=1, radius 2, normalized) ----
constexpr double c_E05 = 0.60653065971263342426;
constexpr double c_E2  = 0.13533528323661269189;
constexpr double c_KS  = 1.0 + 2.0*c_E05 + 2.0*c_E2;
#define K0F ((float)(1.0   / c_KS))
#define K1F ((float)(c_E05 / c_KS))
#define K2F ((float)(c_E2  / c_KS))

// bilateral: w = sc[d2]*exp(-2*df^2) = 2^(CEXP*df^2 + LSC[d2])
#define CEXP  (-2.8853900817779268f)   // -2*log2(e)
#define LSC1  (-0.3205988979944306f)
#define LSC2  (-0.6411977959888612f)
#define LSC3  (-0.9617966939832918f)

#define LOG_SQRT_2PI 0.91893853320467274178f

__device__ __forceinline__ float ex2f(float x) {
    float r; asm("ex2.approx.ftz.f32 %0, %1;" : "=f"(r) : "f"(x)); return r;
}
__device__ __forceinline__ float sigmoidf_fast(float x) {
    return __fdividef(1.0f, 1.0f + ex2f(-1.4426950408889634f * x));
}
__device__ __forceinline__ float axis_sum(int i, int N) {
    float m = 1.f;
    if (i == 0) m -= (K1F + K2F); else if (i == 1) m -= K2F;
    int j = N - 1 - i;
    if (j == 0) m -= (K1F + K2F); else if (j == 1) m -= K2F;
    return m;
}

__global__ void init_kernel(const float* __restrict__ img,
                            const float* __restrict__ h,
                            const float* __restrict__ f1,
                            const float* __restrict__ w0,
                            const float* __restrict__ sw,
                            const float* __restrict__ bw,
                            const float* __restrict__ cm) {
    int i = blockIdx.x * blockDim.x + threadIdx.x;
    if (i >= NVOX) return;
    float cm0 = cm[2] - cm[0];
    float cm1 = cm[3] - cm[1];
    float dA0  = cm0 * sw[0] + cm1 * sw[2];
    float dA1  = cm0 * sw[1] + cm1 * sw[3];
    float dB0  = cm0 * bw[0] + cm1 * bw[2];
    float dB1  = cm0 * bw[1] + cm1 * bw[3];
    float dA1m = dA1 - dA0;
    float dB1m = dB1 - dB0;
    float rB   = dA1m / dB1m;
    if (i == 0) {
        g_coef[0] = rB; g_coef[1] = dB0; g_coef[2] = dB1m;
    }
    int x = i & 127;
    int y = (i >> 7) & 127;
    int z = i >> 14;

    float I  = img[i];
    float d  = h[i + NVOX] - h[i];
    float du = d * (f1[i] - w0[0] + 0.5f*I*I + LOG_SQRT_2PI);
    float S  = axis_sum(z, DD) * axis_sum(y, HH) * axis_sum(x, WW);
    g_duS2[i] = du - (dA0 - rB * dB0) * S;

    float q = sigmoidf_fast(d);
    float s = fmaf(dB1m, q, dB0);
    int p = ((z + 2)*PH + (y + 2))*PW + (x + 4);
    g_pA[p] = make_float2(I, s);
}

template<int LAST>
__global__ void __launch_bounds__(512, 3)
iter_kernel(int flip, float* __restrict__ out,
            const float* __restrict__ f1, int copyf1)
{
    __shared__ float2 ss[8][8][36];      // (I, s), halo2, origin (z0-2, y0-2, x0-2)
    __shared__ float  t1[8][8][32];      // x-blurred s
    __shared__ float  t2[8][4][32];      // xy-blurred s

    const float2* __restrict__ qprev = flip ? g_pB : g_pA;
    float2*       __restrict__ qnext = flip ? g_pA : g_pB;

    const int lane = threadIdx.x;                 // 0..31
    const int ty   = threadIdx.y;                 // 0..3
    const int tz   = threadIdx.z;                 // 0..3
    const int wid  = ty + 4*tz;                   // 0..15
    const int x0 = blockIdx.x << 5;
    const int y0 = blockIdx.y << 2;
    const int z0 = blockIdx.z << 2;

    // padded index of (z0-2, y0-2, x0-2)
    const int pbase = (z0*PH + y0)*PW + x0 + 2;

    // ---- halo load: pure copy, 64 rows (8z x 8y) of 36, 4 rows per warp ----
    #pragma unroll
    for (int k = 0; k < 4; k++) {
        int r  = wid + (k << 4);
        int lz = r >> 3;
        int ly = r & 7;
        int a  = pbase + lz*PPLANE + ly*PW + lane;
        ss[lz][ly][lane] = qprev[a];
        if (lane < 4)
            ss[lz][ly][lane + 32] = qprev[a + 32];
    }
    __syncthreads();

    // ---- x-blur on s: 64 rows, 4 per warp ----
    #pragma unroll
    for (int k = 0; k < 4; k++) {
        int r  = wid + (k << 4);
        int lz = r >> 3;
        int ly = r & 7;
        const float2* row = &ss[lz][ly][lane];
        t1[lz][ly][lane] = K2F*(row[0].y + row[4].y)
                         + K1F*(row[1].y + row[3].y)
                         + K0F* row[2].y;
    }
    __syncthreads();

    // ---- y-blur: 32 rows, 2 per warp ----
    #pragma unroll
    for (int k = 0; k < 2; k++) {
        int r  = wid + (k << 4);
        int lz = r >> 2;
        int yy = r & 3;
        t2[lz][yy][lane] = K2F*(t1[lz][yy  ][lane] + t1[lz][yy+4][lane])
                         + K1F*(t1[lz][yy+1][lane] + t1[lz][yy+3][lane])
                         + K0F* t1[lz][yy+2][lane];
    }
    __syncthreads();

    // ---- z-blur (per-thread): blur_s ----
    float blur_s = K2F*(t2[tz][ty][lane]   + t2[tz+4][ty][lane])
                 + K1F*(t2[tz+1][ty][lane] + t2[tz+3][ty][lane])
                 + K0F* t2[tz+2][ty][lane];

    // ---- bilateral: 27 taps, single uniform path on (I, s) ----
    const float2* C = &ss[tz+1][ty+1][lane+1];
    float2 ctr = C[36*8 + 36 + 1];        // true center (tz+2, ty+2, lane+2)
    const float Ic = ctr.x;
    float den = 1.f;                      // center weight = 1 exactly
    float acc = ctr.y;
    #pragma unroll
    for (int dz = 0; dz <= 2; dz++) {
        #pragma unroll
        for (int dy = 0; dy <= 2; dy++) {
            #pragma unroll
            for (int dx = 0; dx <= 2; dx++) {
                const int d2 = (dz-1)*(dz-1) + (dy-1)*(dy-1) + (dx-1)*(dx-1);
                if (d2 == 0) continue;
                const int off = (dz*8 + dy)*36 + dx;
                const float lsc = (d2 == 1) ? LSC1 : (d2 == 2) ? LSC2 : LSC3;
                float2 nb = C[off];
                float df = Ic - nb.x;
                float w  = ex2f(fmaf(df*df, CEXP, lsc));
                den += w;
                acc = fmaf(w, nb.y, acc);
            }
        }
    }

    // ---- combine + write ----
    const float rB   = g_coef[0];
    const float dB0  = g_coef[1];
    const float dB1m = g_coef[2];
    const int gx = x0 + lane, gy = y0 + ty, gz = z0 + tz;
    const int gi = (gz*HH + gy)*WW + gx;
    float d = g_duS2[gi] - rB*blur_s - __fdividef(acc, den);
    float res = sigmoidf_fast(d);

    if (LAST) {
        out[gi]        = 1.f - res;
        out[NVOX + gi] = res;
        if (copyf1) out[2*NVOX + gi] = f1[gi];
    } else {
        int pc = pbase + (tz+2)*PPLANE + (ty+2)*PW + (lane + 2);
        qnext[pc] = make_float2(Ic, fmaf(dB1m, res, dB0));
    }
}

extern "C" void kernel_launch(void* const* d_in, const int* in_sizes, int n_in,
                              void* d_out, int out_size) {
    const float* img = (const float*)d_in[0];
    const float* h   = (const float*)d_in[1];
    const float* f1  = (const float*)d_in[2];
    const float* w0  = (const float*)d_in[3];
    const float* sw  = (const float*)d_in[4];
    const float* bw  = (const float*)d_in[5];
    const float* cm  = (const float*)d_in[6];
    float* out = (float*)d_out;

    init_kernel<<<NVOX/256, 256>>>(img, h, f1, w0, sw, bw, cm);

    dim3 blk(32, 4, 4);
    dim3 grd(WW/32, HH/4, DD/4);
    int copyf1 = (out_size >= 3 * NVOX) ? 1 : 0;
    iter_kernel<0><<<grd, blk>>>(0, out, f1, copyf1);   // A -> B
    iter_kernel<0><<<grd, blk>>>(1, out, f1, copyf1);   // B -> A
    iter_kernel<0><<<grd, blk>>>(0, out, f1, copyf1);   // A -> B
    iter_kernel<0><<<grd, blk>>>(1, out, f1, copyf1);   // B -> A
    iter_kernel<1><<<grd, blk>>>(0, out, f1, copyf1);   // A -> out
}

// round 7
// speedup vs baseline: 2.3807x; 1.1002x over previous
#include <cuda_runtime.h>

#define DD 64
#define HH 128
#define WW 128
#define NVOX (DD*HH*WW)

// padded layout (zero borders, zero-initialized statics)
#define PH 132
#define PW 136
#define PPLANE (PH*PW)
#define PSZ (68*PPLANE)

// ---- static device state ----
// (I, s) where s = dB1m*q + dB0*m; padding stays (0,0) forever = mask 0.
__device__ float2 g_pA[PSZ];
__device__ float2 g_pB[PSZ];
__device__ float  g_duS2[NVOX];  // du - (dA0 - rB*dB0)*S
__device__ float  g_coef[4];     // rB, dB0, dB1m, -

// ---- blur taps (sigma=1, radius 2, normalized) ----
constexpr double c_E05 = 0.60653065971263342426;
constexpr double c_E2  = 0.13533528323661269189;
constexpr double c_KS  = 1.0 + 2.0*c_E05 + 2.0*c_E2;
#define K0F ((float)(1.0   / c_KS))
#define K1F ((float)(c_E05 / c_KS))
#define K2F ((float)(c_E2  / c_KS))

// bilateral: w = sc[d2]*exp(-2*df^2) = 2^(CEXP*df^2 + LSC[d2])
#define CEXP  (-2.8853900817779268f)   // -2*log2(e)
#define LSC1  (-0.3205988979944306f)
#define LSC2  (-0.6411977959888612f)
#define LSC3  (-0.9617966939832918f)

#define LOG_SQRT_2PI 0.91893853320467274178f

__device__ __forceinline__ float ex2f(float x) {
    float r; asm("ex2.approx.ftz.f32 %0, %1;" : "=f"(r) : "f"(x)); return r;
}
__device__ __forceinline__ float sigmoidf_fast(float x) {
    return __fdividef(1.0f, 1.0f + ex2f(-1.4426950408889634f * x));
}
__device__ __forceinline__ float axis_sum(int i, int N) {
    float m = 1.f;
    if (i == 0) m -= (K1F + K2F); else if (i == 1) m -= K2F;
    int j = N - 1 - i;
    if (j == 0) m -= (K1F + K2F); else if (j == 1) m -= K2F;
    return m;
}

__global__ void init_kernel(const float* __restrict__ img,
                            const float* __restrict__ h,
                            const float* __restrict__ f1,
                            const float* __restrict__ w0,
                            const float* __restrict__ sw,
                            const float* __restrict__ bw,
                            const float* __restrict__ cm) {
    int i = blockIdx.x * blockDim.x + threadIdx.x;
    if (i >= NVOX) return;
    float cm0 = cm[2] - cm[0];
    float cm1 = cm[3] - cm[1];
    float dA0  = cm0 * sw[0] + cm1 * sw[2];
    float dA1  = cm0 * sw[1] + cm1 * sw[3];
    float dB0  = cm0 * bw[0] + cm1 * bw[2];
    float dB1  = cm0 * bw[1] + cm1 * bw[3];
    float dA1m = dA1 - dA0;
    float dB1m = dB1 - dB0;
    float rB   = dA1m / dB1m;
    if (i == 0) {
        g_coef[0] = rB; g_coef[1] = dB0; g_coef[2] = dB1m;
    }
    int x = i & 127;
    int y = (i >> 7) & 127;
    int z = i >> 14;

    float I  = img[i];
    float d  = h[i + NVOX] - h[i];
    float du = d * (f1[i] - w0[0] + 0.5f*I*I + LOG_SQRT_2PI);
    float S  = axis_sum(z, DD) * axis_sum(y, HH) * axis_sum(x, WW);
    g_duS2[i] = du - (dA0 - rB * dB0) * S;

    float q = sigmoidf_fast(d);
    float s = fmaf(dB1m, q, dB0);
    int p = ((z + 2)*PH + (y + 2))*PW + (x + 4);
    g_pA[p] = make_float2(I, s);
}

template<int LAST>
__global__ void __launch_bounds__(512, 3)
iter_kernel(int flip, float* __restrict__ out,
            const float* __restrict__ f1, int copyf1)
{
    // tile: 32 x (x) * 4 (y) * 8 (z); each thread computes 2 adjacent z voxels
    __shared__ float2 ss[12][8][36];     // (I,s): z halo2, y halo2, x halo2
    __shared__ float  t1[12][8][32];     // x-blurred s
    __shared__ float  t2[12][4][32];     // xy-blurred s

    const float2* __restrict__ qprev = flip ? g_pB : g_pA;
    float2*       __restrict__ qnext = flip ? g_pA : g_pB;

    const int lane = threadIdx.x;                 // 0..31
    const int ty   = threadIdx.y;                 // 0..3
    const int tz   = threadIdx.z;                 // 0..3 (z pair index)
    const int tid  = lane + 32*(ty + 4*tz);
    const int wid  = ty + 4*tz;                   // warp id 0..15
    const int x0 = blockIdx.x << 5;
    const int y0 = blockIdx.y << 2;
    const int z0 = blockIdx.z << 3;

    // padded index of (z0-2, y0-2, x0-2)
    const int pbase = (z0*PH + y0)*PW + x0 + 2;

    // ---- halo load: pure copy, 96 rows (12z x 8y) of 36 float2, 6 rows/warp ----
    #pragma unroll
    for (int k = 0; k < 6; k++) {
        int r  = wid + (k << 4);
        int lz = r >> 3;
        int ly = r & 7;
        int a  = pbase + lz*PPLANE + ly*PW + lane;
        ss[lz][ly][lane] = qprev[a];
        if (lane < 4)
            ss[lz][ly][lane + 32] = qprev[a + 32];
    }
    __syncthreads();

    // ---- x-blur on s: 768 quads (12z x 8y x 8q), vectorized ----
    {
        #pragma unroll
        for (int k = 0; k < 2; k++) {
            int qi = tid + (k << 9);
            if (k == 1 && tid >= 256) break;
            int row = qi >> 3;
            int qx  = qi & 7;
            int lz  = row >> 3;
            int ly  = row & 7;
            const float2* rp = &ss[lz][ly][qx << 2];
            float2 a0 = rp[0], a1 = rp[1], a2 = rp[2], a3 = rp[3];
            float2 a4 = rp[4], a5 = rp[5], a6 = rp[6], a7 = rp[7];
            float4 o;
            o.x = K2F*(a0.y + a4.y) + K1F*(a1.y + a3.y) + K0F*a2.y;
            o.y = K2F*(a1.y + a5.y) + K1F*(a2.y + a4.y) + K0F*a3.y;
            o.z = K2F*(a2.y + a6.y) + K1F*(a3.y + a5.y) + K0F*a4.y;
            o.w = K2F*(a3.y + a7.y) + K1F*(a4.y + a6.y) + K0F*a5.y;
            *(float4*)&t1[lz][ly][qx << 2] = o;
        }
    }
    __syncthreads();

    // ---- y-blur: 384 quads (12z x 4y x 8q), vectorized ----
    if (tid < 384) {
        int row = tid >> 3;
        int qx  = tid & 7;
        int lz  = row >> 2;
        int yy  = row & 3;
        float4 r0 = *(const float4*)&t1[lz][yy  ][qx << 2];
        float4 r1 = *(const float4*)&t1[lz][yy+1][qx << 2];
        float4 r2 = *(const float4*)&t1[lz][yy+2][qx << 2];
        float4 r3 = *(const float4*)&t1[lz][yy+3][qx << 2];
        float4 r4 = *(const float4*)&t1[lz][yy+4][qx << 2];
        float4 o;
        o.x = K2F*(r0.x+r4.x) + K1F*(r1.x+r3.x) + K0F*r2.x;
        o.y = K2F*(r0.y+r4.y) + K1F*(r1.y+r3.y) + K0F*r2.y;
        o.z = K2F*(r0.z+r4.z) + K1F*(r1.z+r3.z) + K0F*r2.z;
        o.w = K2F*(r0.w+r4.w) + K1F*(r1.w+r3.w) + K0F*r2.w;
        *(float4*)&t2[lz][yy][qx << 2] = o;
    }
    __syncthreads();

    const int v0 = tz << 1;   // tile z of first voxel in pair

    // ---- z-blur: 6 shared loads serve both voxels ----
    float c0 = t2[v0  ][ty][lane];
    float c1 = t2[v0+1][ty][lane];
    float c2 = t2[v0+2][ty][lane];
    float c3 = t2[v0+3][ty][lane];
    float c4 = t2[v0+4][ty][lane];
    float c5 = t2[v0+5][ty][lane];
    float sp0 = K2F*(c0+c4) + K1F*(c1+c3) + K0F*c2;
    float sp1 = K2F*(c1+c5) + K1F*(c2+c4) + K0F*c3;

    // ---- bilateral for the z pair: 4 planes x 9 taps loaded once ----
    float2 ctr0 = ss[v0+2][ty+2][lane+2];
    float2 ctr1 = ss[v0+3][ty+2][lane+2];
    const float Ic0 = ctr0.x, Ic1 = ctr1.x;
    float den0 = 1.f, acc0 = ctr0.y;
    float den1 = 1.f, acc1 = ctr1.y;

    #pragma unroll
    for (int p = 0; p < 4; p++) {
        #pragma unroll
        for (int r = 0; r < 3; r++) {
            #pragma unroll
            for (int c = 0; c < 3; c++) {
                const int rc2 = (r-1)*(r-1) + (c-1)*(c-1);
                float2 nb = ss[v0+1+p][ty+1+r][lane+1+c];
                if (p <= 2 && !(p == 1 && rc2 == 0)) {      // tap for voxel 0
                    const int d2 = (p-1)*(p-1) + rc2;
                    const float lsc = (d2 == 1) ? LSC1 : (d2 == 2) ? LSC2 : LSC3;
                    float df = Ic0 - nb.x;
                    float w  = ex2f(fmaf(df*df, CEXP, lsc));
                    den0 += w;
                    acc0 = fmaf(w, nb.y, acc0);
                }
                if (p >= 1 && !(p == 2 && rc2 == 0)) {      // tap for voxel 1
                    const int d2 = (p-2)*(p-2) + rc2;
                    const float lsc = (d2 == 1) ? LSC1 : (d2 == 2) ? LSC2 : LSC3;
                    float df = Ic1 - nb.x;
                    float w  = ex2f(fmaf(df*df, CEXP, lsc));
                    den1 += w;
                    acc1 = fmaf(w, nb.y, acc1);
                }
            }
        }
    }

    // ---- combine + write (2 voxels) ----
    const float rB   = g_coef[0];
    const float dB0  = g_coef[1];
    const float dB1m = g_coef[2];
    const int gx = x0 + lane, gy = y0 + ty, gz = z0 + v0;
    const int gi0 = (gz*HH + gy)*WW + gx;
    const int gi1 = gi0 + HH*WW;

    float d0 = g_duS2[gi0] - rB*sp0 - __fdividef(acc0, den0);
    float d1 = g_duS2[gi1] - rB*sp1 - __fdividef(acc1, den1);
    float res0 = sigmoidf_fast(d0);
    float res1 = sigmoidf_fast(d1);

    if (LAST) {
        out[gi0]        = 1.f - res0;
        out[NVOX + gi0] = res0;
        out[gi1]        = 1.f - res1;
        out[NVOX + gi1] = res1;
        if (copyf1) {
            out[2*NVOX + gi0] = f1[gi0];
            out[2*NVOX + gi1] = f1[gi1];
        }
    } else {
        int pc = pbase + (v0+2)*PPLANE + (ty+2)*PW + (lane + 2);
        qnext[pc]          = make_float2(Ic0, fmaf(dB1m, res0, dB0));
        qnext[pc + PPLANE] = make_float2(Ic1, fmaf(dB1m, res1, dB0));
    }
}

extern "C" void kernel_launch(void* const* d_in, const int* in_sizes, int n_in,
                              void* d_out, int out_size) {
    const float* img = (const float*)d_in[0];
    const float* h   = (const float*)d_in[1];
    const float* f1  = (const float*)d_in[2];
    const float* w0  = (const float*)d_in[3];
    const float* sw  = (const float*)d_in[4];
    const float* bw  = (const float*)d_in[5];
    const float* cm  = (const float*)d_in[6];
    float* out = (float*)d_out;

    init_kernel<<<NVOX/256, 256>>>(img, h, f1, w0, sw, bw, cm);

    dim3 blk(32, 4, 4);
    dim3 grd(WW/32, HH/4, DD/8);
    int copyf1 = (out_size >= 3 * NVOX) ? 1 : 0;
    iter_kernel<0><<<grd, blk>>>(0, out, f1, copyf1);   // A -> B
    iter_kernel<0><<<grd, blk>>>(1, out, f1, copyf1);   // B -> A
    iter_kernel<0><<<grd, blk>>>(0, out, f1, copyf1);   // A -> B
    iter_kernel<0><<<grd, blk>>>(1, out, f1, copyf1);   // B -> A
    iter_kernel<1><<<grd, blk>>>(0, out, f1, copyf1);   // A -> out
}

// round 9
// speedup vs baseline: 3.3361x; 1.4013x over previous
#include <cuda_runtime.h>

#define DD 64
#define HH 128
#define WW 128
#define NVOX (DD*HH*WW)

// padded layout (zero borders, zero-initialized statics)
#define PH 132
#define PW 136
#define PPLANE (PH*PW)
#define PSZ (68*PPLANE)

// ---- static device state ----
// (I, s) where s = dB1m*q + dB0*m; padding stays (0,0) forever = mask 0.
__device__ float2 g_pA[PSZ];
__device__ float2 g_pB[PSZ];
__device__ float  g_duS2[NVOX];  // du - (dA0 - rB*dB0)*S
__device__ float  g_coef[4];     // rB, dB0, dB1m, -

// ---- blur taps (sigma=1, radius 2, normalized) ----
constexpr double c_E05 = 0.60653065971263342426;
constexpr double c_E2  = 0.13533528323661269189;
constexpr double c_KS  = 1.0 + 2.0*c_E05 + 2.0*c_E2;
#define K0F ((float)(1.0   / c_KS))
#define K1F ((float)(c_E05 / c_KS))
#define K2F ((float)(c_E2  / c_KS))

// bilateral: w = sc[d2]*exp(-2*df^2) = 2^(CEXP*df^2 + LSC[d2])
#define CEXP  (-2.8853900817779268f)   // -2*log2(e)
#define LSC1  (-0.3205988979944306f)
#define LSC2  (-0.6411977959888612f)
#define LSC3  (-0.9617966939832918f)

#define LOG_SQRT_2PI 0.91893853320467274178f

__device__ __forceinline__ float ex2f(float x) {
    float r; asm("ex2.approx.ftz.f32 %0, %1;" : "=f"(r) : "f"(x)); return r;
}
__device__ __forceinline__ float sigmoidf_fast(float x) {
    return __fdividef(1.0f, 1.0f + ex2f(-1.4426950408889634f * x));
}
__device__ __forceinline__ float axis_sum(int i, int N) {
    float m = 1.f;
    if (i == 0) m -= (K1F + K2F); else if (i == 1) m -= K2F;
    int j = N - 1 - i;
    if (j == 0) m -= (K1F + K2F); else if (j == 1) m -= K2F;
    return m;
}

__global__ void init_kernel(const float* __restrict__ img,
                            const float* __restrict__ h,
                            const float* __restrict__ f1,
                            const float* __restrict__ w0,
                            const float* __restrict__ sw,
                            const float* __restrict__ bw,
                            const float* __restrict__ cm) {
    int i = blockIdx.x * blockDim.x + threadIdx.x;
    if (i >= NVOX) return;
    float cm0 = cm[2] - cm[0];
    float cm1 = cm[3] - cm[1];
    float dA0  = cm0 * sw[0] + cm1 * sw[2];
    float dA1  = cm0 * sw[1] + cm1 * sw[3];
    float dB0  = cm0 * bw[0] + cm1 * bw[2];
    float dB1  = cm0 * bw[1] + cm1 * bw[3];
    float dA1m = dA1 - dA0;
    float dB1m = dB1 - dB0;
    float rB   = dA1m / dB1m;
    if (i == 0) {
        g_coef[0] = rB; g_coef[1] = dB0; g_coef[2] = dB1m;
    }
    int x = i & 127;
    int y = (i >> 7) & 127;
    int z = i >> 14;

    float I  = img[i];
    float d  = h[i + NVOX] - h[i];
    float du = d * (f1[i] - w0[0] + 0.5f*I*I + LOG_SQRT_2PI);
    float S  = axis_sum(z, DD) * axis_sum(y, HH) * axis_sum(x, WW);
    g_duS2[i] = du - (dA0 - rB * dB0) * S;

    float q = sigmoidf_fast(d);
    float s = fmaf(dB1m, q, dB0);
    int p = ((z + 2)*PH + (y + 2))*PW + (x + 4);
    g_pA[p] = make_float2(I, s);
}

// smem geometry: sI/sS [12 z][8 y][36 x] scalar planes (3456 floats each)
#define SROW 36
#define SPL  (8*36)     // z-plane stride
#define POOLSZ (2*3456)

template<int LAST>
__global__ void __launch_bounds__(256, 6)
iter_kernel(int flip, float* __restrict__ out,
            const float* __restrict__ f1, int copyf1)
{
    __shared__ __align__(16) float pool[POOLSZ];
    float* sI = pool;            // [12][8][36]; later aliased by t1 [12][8][32]
    float* sS = pool + 3456;     // [12][8][36]; later aliased by t2 [12][4][32]
    float* t1 = pool;
    float* t2 = pool + 3456;

    const float2* __restrict__ qprev = flip ? g_pB : g_pA;
    float2*       __restrict__ qnext = flip ? g_pA : g_pB;

    const int lane = threadIdx.x;                 // 0..31 (x)
    const int ty   = threadIdx.y;                 // 0..1  (y pair)
    const int tz   = threadIdx.z;                 // 0..3  (z pair)
    const int tid  = lane + 32*(ty + 2*tz);
    const int wid  = ty + 2*tz;                   // warp 0..7
    const int x0 = blockIdx.x << 5;
    const int y0 = blockIdx.y << 2;
    const int z0 = blockIdx.z << 3;
    const int wy = ty << 1;                       // tile y base of pair
    const int vz = tz << 1;                       // tile z base of pair

    // padded index of (z0-2, y0-2, x0-2)
    const int pbase = (z0*PH + y0)*PW + x0 + 2;

    // ---- halo load: 96 rows (12z x 8y) x 36, split into scalar planes ----
    #pragma unroll
    for (int k = 0; k < 12; k++) {
        int r  = wid + (k << 3);      // 0..95
        int lz = r >> 3;
        int ly = r & 7;
        int a  = pbase + lz*PPLANE + ly*PW + lane;
        int si = lz*SPL + ly*SROW + lane;
        float2 v = qprev[a];
        sI[si] = v.x;
        sS[si] = v.y;
        if (lane < 4) {
            float2 v2 = qprev[a + 32];
            sI[si + 32] = v2.x;
            sS[si + 32] = v2.y;
        }
    }
    __syncthreads();

    // ---- bilateral 2x2 quad: 48 shared positions serve 104 taps ----
    float Ic[2][2], den[2][2], acc[2][2], pb[2][2];
    #pragma unroll
    for (int zi = 0; zi < 2; zi++)
        #pragma unroll
        for (int yi = 0; yi < 2; yi++) {
            int c = (vz+2+zi)*SPL + (wy+2+yi)*SROW + lane + 2;
            Ic[zi][yi]  = sI[c];
            acc[zi][yi] = sS[c];      // center weight = 1 exactly
            den[zi][yi] = 1.f;
        }
    #pragma unroll
    for (int pp = 0; pp < 4; pp++) {
        #pragma unroll
        for (int rr = 0; rr < 4; rr++) {
            #pragma unroll
            for (int cc = 0; cc < 3; cc++) {
                const int idx = (vz+1+pp)*SPL + (wy+1+rr)*SROW + lane + 1 + cc;
                float Iv = sI[idx];
                float Sv = sS[idx];
                #pragma unroll
                for (int zi = 0; zi < 2; zi++) {
                    const int dz = pp - 1 - zi;
                    if (dz < -1 || dz > 1) continue;
                    #pragma unroll
                    for (int yi = 0; yi < 2; yi++) {
                        const int dy = rr - 1 - yi;
                        if (dy < -1 || dy > 1) continue;
                        const int d2 = dz*dz + dy*dy + (cc-1)*(cc-1);
                        if (d2 == 0) continue;
                        const float lsc = (d2 == 1) ? LSC1 : (d2 == 2) ? LSC2 : LSC3;
                        float df = Ic[zi][yi] - Iv;
                        float w  = ex2f(fmaf(df*df, CEXP, lsc));
                        den[zi][yi] += w;
                        acc[zi][yi] = fmaf(w, Sv, acc[zi][yi]);
                    }
                }
            }
        }
    }
    #pragma unroll
    for (int zi = 0; zi < 2; zi++)
        #pragma unroll
        for (int yi = 0; yi < 2; yi++)
            pb[zi][yi] = __fdividef(acc[zi][yi], den[zi][yi]);
    __syncthreads();   // all sI reads done; t1 may overwrite

    // ---- x-blur on sS -> t1 [12][8][32]: 768 quads, 3 per thread ----
    // output j = qx*4 + {0,1,2,3} (center at sS column j+2); needs sS[j..j+4]
    #pragma unroll
    for (int k = 0; k < 3; k++) {
        int e   = tid + (k << 8);
        int row = e >> 3;             // 0..95
        int qx  = e & 7;
        const float* rp = sS + row*SROW + (qx << 2);
        float4 a = *(const float4*)rp;        // s[j .. j+3]
        float4 b = *(const float4*)(rp + 4);  // s[j+4 .. j+7]
        float4 o;
        o.x = K2F*(a.x + b.x) + K1F*(a.y + a.w) + K0F*a.z;
        o.y = K2F*(a.y + b.y) + K1F*(a.z + b.x) + K0F*a.w;
        o.z = K2F*(a.z + b.z) + K1F*(a.w + b.y) + K0F*b.x;
        o.w = K2F*(a.w + b.w) + K1F*(b.x + b.z) + K0F*b.y;
        *(float4*)(t1 + row*32 + (qx << 2)) = o;
    }
    __syncthreads();   // all sS reads done; t2 may overwrite

    // ---- y-blur t1 -> t2 [12][4][32]: 384 quads (256 + 128) ----
    {
        int r2 = tid >> 3;            // 0..31
        int q2 = tid & 7;
        int lz = r2 >> 2;
        int yy = r2 & 3;
        const float* bp = t1 + (lz*8 + yy)*32 + (q2 << 2);
        float4 r0 = *(const float4*)(bp);
        float4 r1 = *(const float4*)(bp + 32);
        float4 r2v = *(const float4*)(bp + 64);
        float4 r3 = *(const float4*)(bp + 96);
        float4 r4 = *(const float4*)(bp + 128);
        float4 o;
        o.x = K2F*(r0.x+r4.x) + K1F*(r1.x+r3.x) + K0F*r2v.x;
        o.y = K2F*(r0.y+r4.y) + K1F*(r1.y+r3.y) + K0F*r2v.y;
        o.z = K2F*(r0.z+r4.z) + K1F*(r1.z+r3.z) + K0F*r2v.z;
        o.w = K2F*(r0.w+r4.w) + K1F*(r1.w+r3.w) + K0F*r2v.w;
        *(float4*)(t2 + (lz*4 + yy)*32 + (q2 << 2)) = o;
    }
    if (tid < 128) {
        int e2 = tid + 256;
        int r2 = e2 >> 3;             // 32..47
        int q2 = e2 & 7;
        int lz = r2 >> 2;
        int yy = r2 & 3;
        const float* bp = t1 + (lz*8 + yy)*32 + (q2 << 2);
        float4 r0 = *(const float4*)(bp);
        float4 r1 = *(const float4*)(bp + 32);
        float4 r2v = *(const float4*)(bp + 64);
        float4 r3 = *(const float4*)(bp + 96);
        float4 r4 = *(const float4*)(bp + 128);
        float4 o;
        o.x = K2F*(r0.x+r4.x) + K1F*(r1.x+r3.x) + K0F*r2v.x;
        o.y = K2F*(r0.y+r4.y) + K1F*(r1.y+r3.y) + K0F*r2v.y;
        o.z = K2F*(r0.z+r4.z) + K1F*(r1.z+r3.z) + K0F*r2v.z;
        o.w = K2F*(r0.w+r4.w) + K1F*(r1.w+r3.w) + K0F*r2v.w;
        *(float4*)(t2 + (lz*4 + yy)*32 + (q2 << 2)) = o;
    }
    __syncthreads();

    // ---- z-blur + combine + write (4 voxels) ----
    const float rB   = g_coef[0];
    const float dB0  = g_coef[1];
    const float dB1m = g_coef[2];

    #pragma unroll
    for (int yi = 0; yi < 2; yi++) {
        float c0 = t2[((vz+0)*4 + wy+yi)*32 + lane];
        float c1 = t2[((vz+1)*4 + wy+yi)*32 + lane];
        float c2 = t2[((vz+2)*4 + wy+yi)*32 + lane];
        float c3 = t2[((vz+3)*4 + wy+yi)*32 + lane];
        float c4 = t2[((vz+4)*4 + wy+yi)*32 + lane];
        float c5 = t2[((vz+5)*4 + wy+yi)*32 + lane];
        float sp0 = K2F*(c0+c4) + K1F*(c1+c3) + K0F*c2;
        float sp1 = K2F*(c1+c5) + K1F*(c2+c4) + K0F*c3;

        const int gy = y0 + wy + yi;
        const int gz = z0 + vz;
        const int gi0 = (gz*HH + gy)*WW + x0 + lane;
        const int gi1 = gi0 + HH*WW;

        float d0 = g_duS2[gi0] - rB*sp0 - pb[0][yi];
        float d1 = g_duS2[gi1] - rB*sp1 - pb[1][yi];
        float res0 = sigmoidf_fast(d0);
        float res1 = sigmoidf_fast(d1);

        if (LAST) {
            out[gi0]        = 1.f - res0;
            out[NVOX + gi0] = res0;
            out[gi1]        = 1.f - res1;
            out[NVOX + gi1] = res1;
            if (copyf1) {
                out[2*NVOX + gi0] = f1[gi0];
                out[2*NVOX + gi1] = f1[gi1];
            }
        } else {
            int pc = pbase + (vz+2)*PPLANE + (wy+yi+2)*PW + lane + 2;
            qnext[pc]          = make_float2(Ic[0][yi], fmaf(dB1m, res0, dB0));
            qnext[pc + PPLANE] = make_float2(Ic[1][yi], fmaf(dB1m, res1, dB0));
        }
    }
}

extern "C" void kernel_launch(void* const* d_in, const int* in_sizes, int n_in,
                              void* d_out, int out_size) {
    const float* img = (const float*)d_in[0];
    const float* h   = (const float*)d_in[1];
    const float* f1  = (const float*)d_in[2];
    const float* w0  = (const float*)d_in[3];
    const float* sw  = (const float*)d_in[4];
    const float* bw  = (const float*)d_in[5];
    const float* cm  = (const float*)d_in[6];
    float* out = (float*)d_out;

    init_kernel<<<NVOX/256, 256>>>(img, h, f1, w0, sw, bw, cm);

    dim3 blk(32, 2, 4);
    dim3 grd(WW/32, HH/4, DD/8);
    int copyf1 = (out_size >= 3 * NVOX) ? 1 : 0;
    iter_kernel<0><<<grd, blk>>>(0, out, f1, copyf1);   // A -> B
    iter_kernel<0><<<grd, blk>>>(1, out, f1, copyf1);   // B -> A
    iter_kernel<0><<<grd, blk>>>(0, out, f1, copyf1);   // A -> B
    iter_kernel<0><<<grd, blk>>>(1, out, f1, copyf1);   // B -> A
    iter_kernel<1><<<grd, blk>>>(0, out, f1, copyf1);   // A -> out
}